// round 15
// baseline (speedup 1.0000x reference)
#include <cuda_runtime.h>
#include <cuda_fp16.h>
#include <cstdint>

#define NE 600000
#define NN 50000
#define DIM 128
#define NTHREADS 1024
#define ETHREADS 512
#define ETM 128
#define NSM 152

// Scratch for node projections (fp16 storage halves gather traffic)
__device__ __half g_sproj[(size_t)NN * DIM];
__device__ __half g_dproj[(size_t)NN * DIM];

// ---------------- common helpers ----------------
__device__ __forceinline__ uint32_t smem_u32(const void* p) {
    uint32_t a;
    asm("{ .reg .u64 t; cvta.to.shared.u64 t, %1; cvt.u32.u64 %0, t; }" : "=r"(a) : "l"(p));
    return a;
}

// Swizzled tile layout: rows x 128 fp16, row stride 256B.
// 16B chunk index c (0..15) -> (c&8) | ((c ^ r) & 7): ldmatrix conflict-free.
__device__ __forceinline__ uint32_t swz(int r, int kb) {
    int chunk = kb >> 4;
    int c2 = (chunk & 8) | ((chunk ^ r) & 7);
    return (uint32_t)(r * 256 + c2 * 16 + (kb & 15));
}

// load 128x128 fp32 row-major matrix, convert to fp16 swizzled tile
__device__ __forceinline__ void load_matrix_f16(char* dstB, const float* __restrict__ W,
                                                int t, int nthr) {
    for (int p = t; p < DIM * (DIM / 4); p += nthr) {
        int r = p >> 5, c4 = p & 31;
        float4 v = reinterpret_cast<const float4*>(W)[p];
        __half2 p0 = __floats2half2_rn(v.x, v.y);
        __half2 p1 = __floats2half2_rn(v.z, v.w);
        uint32_t o = swz(r, c4 * 8);
        *reinterpret_cast<__half2*>(dstB + o)     = p0;
        *reinterpret_cast<__half2*>(dstB + o + 4) = p1;
    }
}

__device__ __forceinline__ void ldsm4(uint32_t addr, uint32_t r[4]) {
    asm volatile("ldmatrix.sync.aligned.m8n8.x4.shared.b16 {%0,%1,%2,%3}, [%4];"
                 : "=r"(r[0]), "=r"(r[1]), "=r"(r[2]), "=r"(r[3]) : "r"(addr));
}
__device__ __forceinline__ void mma16816(float c[4], const uint32_t a[4],
                                         uint32_t b0, uint32_t b1) {
    asm volatile("mma.sync.aligned.m16n8k16.row.col.f32.f16.f16.f32 "
                 "{%0,%1,%2,%3}, {%4,%5,%6,%7}, {%8,%9}, {%0,%1,%2,%3};"
                 : "+f"(c[0]), "+f"(c[1]), "+f"(c[2]), "+f"(c[3])
                 : "r"(a[0]), "r"(a[1]), "r"(a[2]), "r"(a[3]), "r"(b0), "r"(b1));
}

// silu(x) = x * (0.5*tanh(0.5x) + 0.5): 1 MUFU + 3 fma-pipe ops, no divide.
__device__ __forceinline__ float silu_f32(float x) {
    float th;
    float arg = 0.5f * x;
    asm("tanh.approx.f32 %0, %1;" : "=f"(th) : "f"(arg));
    return x * fmaf(0.5f, th, 0.5f);
}

// Warp GEMM: D(M32xN32) = A(M32xK128) * W^T(K128xN32), single fp16 term.
__device__ __forceinline__ void warp_gemm_f16_n32(
    uint32_t aB, uint32_t wB, int wm, int wn, int lane, float acc[2][4][4])
{
    #pragma unroll
    for (int mt = 0; mt < 2; mt++)
        #pragma unroll
        for (int n8 = 0; n8 < 4; n8++)
            #pragma unroll
            for (int c = 0; c < 4; c++) acc[mt][n8][c] = 0.f;

    int arow[2];
    #pragma unroll
    for (int mt = 0; mt < 2; mt++)
        arow[mt] = wm * 32 + mt * 16 + ((lane >> 3) & 1) * 8 + (lane & 7);
    const int akhi = (lane >> 4) * 8;
    int brow[2];
    #pragma unroll
    for (int np = 0; np < 2; np++)
        brow[np] = wn * 32 + np * 16 + (lane >> 4) * 8 + (lane & 7);
    const int bkhi = ((lane >> 3) & 1) * 8;

    #pragma unroll
    for (int ks = 0; ks < 8; ks++) {
        const int k0 = ks * 16;
        uint32_t a[2][4], b[2][4];
        #pragma unroll
        for (int mt = 0; mt < 2; mt++)
            ldsm4(aB + swz(arow[mt], (k0 + akhi) * 2), a[mt]);
        #pragma unroll
        for (int np = 0; np < 2; np++)
            ldsm4(wB + swz(brow[np], (k0 + bkhi) * 2), b[np]);
        #pragma unroll
        for (int np = 0; np < 2; np++)
            #pragma unroll
            for (int mt = 0; mt < 2; mt++) {
                mma16816(acc[mt][2 * np],     a[mt], b[np][0], b[np][1]);
                mma16816(acc[mt][2 * np + 1], a[mt], b[np][2], b[np][3]);
            }
    }
}

// Warp GEMM: D(M32xN16), node kernel (4x8 warp grid, 1024 threads).
__device__ __forceinline__ void warp_gemm_f16_n16(
    uint32_t aB, uint32_t wB, int wm, int wn, int lane, float acc[2][2][4])
{
    #pragma unroll
    for (int mt = 0; mt < 2; mt++)
        #pragma unroll
        for (int n8 = 0; n8 < 2; n8++)
            #pragma unroll
            for (int c = 0; c < 4; c++) acc[mt][n8][c] = 0.f;

    int arow[2];
    #pragma unroll
    for (int mt = 0; mt < 2; mt++)
        arow[mt] = wm * 32 + mt * 16 + ((lane >> 3) & 1) * 8 + (lane & 7);
    const int akhi = (lane >> 4) * 8;
    const int brow = wn * 16 + (lane >> 4) * 8 + (lane & 7);
    const int bkhi = ((lane >> 3) & 1) * 8;

    #pragma unroll
    for (int ks = 0; ks < 8; ks++) {
        const int k0 = ks * 16;
        uint32_t a[2][4], b[4];
        #pragma unroll
        for (int mt = 0; mt < 2; mt++)
            ldsm4(aB + swz(arow[mt], (k0 + akhi) * 2), a[mt]);
        ldsm4(wB + swz(brow, (k0 + bkhi) * 2), b);
        #pragma unroll
        for (int mt = 0; mt < 2; mt++) {
            mma16816(acc[mt][0], a[mt], b[0], b[1]);
            mma16816(acc[mt][1], a[mt], b[2], b[3]);
        }
    }
}

// ================= tensor node kernel (fp16 single-term, fp16 output) =================
#define NOFF_WS 0
#define NOFF_WD 32768
#define NOFF_A  65536
#define NODE_SMEM_BYTES (98304 + 1024)
#define NTILES_N ((NN + 127) / 128)

__global__ void __launch_bounds__(NTHREADS, 1)
node_mma_kernel(const float* __restrict__ nfeat,
                const float* __restrict__ W_s, const float* __restrict__ W_d)
{
    extern __shared__ char smem_raw[];
    char* ab = (char*)(((uintptr_t)smem_raw + 1023) & ~(uintptr_t)1023);
    const int t = threadIdx.x;
    const int wid = t >> 5, lane = t & 31;
    const int wm = wid & 3, wn = wid >> 2;
    const int quad = lane >> 2, qt = lane & 3;

    const uint32_t u_a  = smem_u32(ab + NOFF_A);
    const uint32_t u_ws = smem_u32(ab + NOFF_WS);
    const uint32_t u_wd = smem_u32(ab + NOFF_WD);

    load_matrix_f16(ab + NOFF_WS, W_s, t, NTHREADS);
    load_matrix_f16(ab + NOFF_WD, W_d, t, NTHREADS);

    for (int tile = blockIdx.x; tile < NTILES_N; tile += gridDim.x) {
        const int n0 = tile * 128;
        __syncthreads();
        for (int p = t; p < DIM * 32; p += NTHREADS) {
            int r = p >> 5, c4 = p & 31;
            int n = n0 + r;
            float4 v = make_float4(0.f, 0.f, 0.f, 0.f);
            if (n < NN) v = reinterpret_cast<const float4*>(nfeat)[(size_t)n * 32 + c4];
            uint32_t o = swz(r, c4 * 8);
            *reinterpret_cast<__half2*>(ab + NOFF_A + o)     = __floats2half2_rn(v.x, v.y);
            *reinterpret_cast<__half2*>(ab + NOFF_A + o + 4) = __floats2half2_rn(v.z, v.w);
        }
        __syncthreads();

        float acc[2][2][4];
        warp_gemm_f16_n16(u_a, u_ws, wm, wn, lane, acc);
        #pragma unroll
        for (int mt = 0; mt < 2; mt++)
            #pragma unroll
            for (int rh = 0; rh < 2; rh++) {
                int n = n0 + wm * 32 + mt * 16 + quad + rh * 8;
                if (n < NN)
                    #pragma unroll
                    for (int n8 = 0; n8 < 2; n8++) {
                        int col = wn * 16 + n8 * 8 + 2 * qt;
                        *reinterpret_cast<__half2*>(&g_sproj[(size_t)n * DIM + col]) =
                            __floats2half2_rn(acc[mt][n8][rh * 2], acc[mt][n8][rh * 2 + 1]);
                    }
            }

        warp_gemm_f16_n16(u_a, u_wd, wm, wn, lane, acc);
        #pragma unroll
        for (int mt = 0; mt < 2; mt++)
            #pragma unroll
            for (int rh = 0; rh < 2; rh++) {
                int n = n0 + wm * 32 + mt * 16 + quad + rh * 8;
                if (n < NN)
                    #pragma unroll
                    for (int n8 = 0; n8 < 2; n8++) {
                        int col = wn * 16 + n8 * 8 + 2 * qt;
                        *reinterpret_cast<__half2*>(&g_dproj[(size_t)n * DIM + col]) =
                            __floats2half2_rn(acc[mt][n8][rh * 2], acc[mt][n8][rh * 2 + 1]);
                    }
            }
    }
}

// ====== mma.sync edge kernel (fp16 single-term, 512 threads, 2 CTAs/SM) ======
#define OFF_W1   0
#define OFF_W2   32768
#define OFF_A    65536    // 128*256 = 32768
#define OFF_B1   98304
#define OFF_BO   98816
#define OFF_GM   99328
#define OFF_BT   99840
#define OFF_RSUM 100352   // float[4][128] = 2048
#define OFF_RSQ  102400   // 2048
#define OFF_SRC  104448   // int[128]
#define OFF_DST  104960
#define EDGE_SMEM_BYTES (105472 + 1024)

#define NTILES_E ((NE + ETM - 1) / ETM)   // 4688

__global__ void __launch_bounds__(ETHREADS, 2)
edge_mma_kernel(const float* __restrict__ efeat,
                const int* __restrict__ src, const int* __restrict__ dst,
                const float* __restrict__ W_e, const float* __restrict__ b1,
                const float* __restrict__ W_o, const float* __restrict__ b_o,
                const float* __restrict__ gamma, const float* __restrict__ beta,
                float* __restrict__ out)
{
    extern __shared__ char smem_raw[];
    char* ab = (char*)(((uintptr_t)smem_raw + 1023) & ~(uintptr_t)1023);
    const int t = threadIdx.x;
    const int wid = t >> 5, lane = t & 31;
    const int wm = wid & 3, wn = wid >> 2;   // 4(M) x 4(N) warp grid, M32 x N32 tiles

    const uint32_t u_a  = smem_u32(ab + OFF_A);
    const uint32_t u_w1 = smem_u32(ab + OFF_W1);
    const uint32_t u_w2 = smem_u32(ab + OFF_W2);

    float* b1s = (float*)(ab + OFF_B1);
    float* bos = (float*)(ab + OFF_BO);
    float* gms = (float*)(ab + OFF_GM);
    float* bts = (float*)(ab + OFF_BT);
    float* rsum = (float*)(ab + OFF_RSUM);
    float* rsq  = (float*)(ab + OFF_RSQ);
    int* srcS = (int*)(ab + OFF_SRC);
    int* dstS = (int*)(ab + OFF_DST);

    load_matrix_f16(ab + OFF_W1, W_e, t, ETHREADS);
    load_matrix_f16(ab + OFF_W2, W_o, t, ETHREADS);
    if (t < 128) { b1s[t] = b1[t]; bos[t] = b_o[t]; gms[t] = gamma[t]; bts[t] = beta[t]; }

    const int quad = lane >> 2, qt = lane & 3;

    for (int tile = blockIdx.x; tile < NTILES_E; tile += gridDim.x) {
        const int e0 = tile * ETM;
        __syncthreads();  // previous tile fully consumed

        // ---- load + convert efeat tile; load indices
        for (int p = t; p < ETM * 32; p += ETHREADS) {
            int r = p >> 5, c4 = p & 31;
            int e = e0 + r;
            float4 v = make_float4(0.f, 0.f, 0.f, 0.f);
            if (e < NE) v = reinterpret_cast<const float4*>(efeat)[(size_t)e * 32 + c4];
            uint32_t o = swz(r, c4 * 8);
            *reinterpret_cast<__half2*>(ab + OFF_A + o)     = __floats2half2_rn(v.x, v.y);
            *reinterpret_cast<__half2*>(ab + OFF_A + o + 4) = __floats2half2_rn(v.z, v.w);
        }
        if (t < ETM) {
            int e = e0 + t;
            srcS[t] = (e < NE) ? src[e] : 0;
            dstS[t] = (e < NE) ? dst[e] : 0;
        }
        __syncthreads();

        // ---- GEMM1
        float acc[2][4][4];
        warp_gemm_f16_n32(u_a, u_w1, wm, wn, lane, acc);
        __syncthreads();  // all warps done reading A before H overwrite

        // ---- epilogue 1: + b1 + gathers (fp16 tables, fp32 sum), SiLU (tanh) -> H
        #pragma unroll
        for (int mt = 0; mt < 2; mt++) {
            #pragma unroll
            for (int rh = 0; rh < 2; rh++) {
                int row = wm * 32 + mt * 16 + quad + rh * 8;
                const __half2* sp = reinterpret_cast<const __half2*>(
                    g_sproj + (size_t)srcS[row] * DIM);
                const __half2* dp = reinterpret_cast<const __half2*>(
                    g_dproj + (size_t)dstS[row] * DIM);
                #pragma unroll
                for (int n8 = 0; n8 < 4; n8++) {
                    int col = wn * 32 + n8 * 8 + 2 * qt;
                    float2 s2 = __half22float2(sp[col >> 1]);
                    float2 d2 = __half22float2(dp[col >> 1]);
                    float2 b2 = *reinterpret_cast<const float2*>(&b1s[col]);
                    float x0 = acc[mt][n8][rh * 2 + 0] + b2.x + s2.x + d2.x;
                    float x1 = acc[mt][n8][rh * 2 + 1] + b2.y + s2.y + d2.y;
                    float v0 = silu_f32(x0);
                    float v1 = silu_f32(x1);
                    *reinterpret_cast<__half2*>(ab + OFF_A + swz(row, col * 2)) =
                        __floats2half2_rn(v0, v1);
                }
            }
        }
        __syncthreads();

        // ---- GEMM2
        warp_gemm_f16_n32(u_a, u_w2, wm, wn, lane, acc);

        // ---- epilogue 2: + b_o, LayerNorm partials (32-col group per warp)
        #pragma unroll
        for (int mt = 0; mt < 2; mt++) {
            #pragma unroll
            for (int rh = 0; rh < 2; rh++) {
                int row = wm * 32 + mt * 16 + quad + rh * 8;
                float s = 0.f, q = 0.f;
                #pragma unroll
                for (int n8 = 0; n8 < 4; n8++) {
                    int col = wn * 32 + n8 * 8 + 2 * qt;
                    float2 b2 = *reinterpret_cast<const float2*>(&bos[col]);
                    float v0 = acc[mt][n8][rh * 2 + 0] + b2.x;
                    float v1 = acc[mt][n8][rh * 2 + 1] + b2.y;
                    acc[mt][n8][rh * 2 + 0] = v0;
                    acc[mt][n8][rh * 2 + 1] = v1;
                    s += v0 + v1;
                    q += v0 * v0 + v1 * v1;
                }
                s += __shfl_xor_sync(0xffffffffu, s, 1);
                s += __shfl_xor_sync(0xffffffffu, s, 2);
                q += __shfl_xor_sync(0xffffffffu, q, 1);
                q += __shfl_xor_sync(0xffffffffu, q, 2);
                if (qt == 0) {
                    rsum[wn * ETM + row] = s;
                    rsq[wn * ETM + row] = q;
                }
            }
        }
        __syncthreads();

        // ---- normalize + affine + residual + store
        #pragma unroll
        for (int mt = 0; mt < 2; mt++) {
            #pragma unroll
            for (int rh = 0; rh < 2; rh++) {
                int row = wm * 32 + mt * 16 + quad + rh * 8;
                int e = e0 + row;
                if (e >= NE) continue;
                float ts = rsum[row] + rsum[ETM + row] + rsum[2 * ETM + row] + rsum[3 * ETM + row];
                float tq = rsq[row] + rsq[ETM + row] + rsq[2 * ETM + row] + rsq[3 * ETM + row];
                float mean = ts * (1.0f / 128.0f);
                float var = tq * (1.0f / 128.0f) - mean * mean;
                float rstd = rsqrtf(var + 1e-5f);
                #pragma unroll
                for (int n8 = 0; n8 < 4; n8++) {
                    int col = wn * 32 + n8 * 8 + 2 * qt;
                    float2 g2 = *reinterpret_cast<const float2*>(&gms[col]);
                    float2 t2 = *reinterpret_cast<const float2*>(&bts[col]);
                    float2 r2 = *reinterpret_cast<const float2*>(&efeat[(size_t)e * DIM + col]);
                    float o0 = (acc[mt][n8][rh * 2 + 0] - mean) * rstd * g2.x + t2.x + r2.x;
                    float o1 = (acc[mt][n8][rh * 2 + 1] - mean) * rstd * g2.y + t2.y + r2.y;
                    *reinterpret_cast<float2*>(&out[(size_t)e * DIM + col]) = make_float2(o0, o1);
                }
            }
        }
    }
}

extern "C" void kernel_launch(void* const* d_in, const int* in_sizes, int n_in,
                              void* d_out, int out_size) {
    const float* efeat = (const float*)d_in[0];
    const float* nfeat = (const float*)d_in[1];
    const int*   src   = (const int*)d_in[2];
    const int*   dst   = (const int*)d_in[3];
    const float* W_e   = (const float*)d_in[4];
    const float* W_s   = (const float*)d_in[5];
    const float* W_d   = (const float*)d_in[6];
    const float* b1    = (const float*)d_in[7];
    const float* W_o   = (const float*)d_in[8];
    const float* b_o   = (const float*)d_in[9];
    const float* gamma = (const float*)d_in[10];
    const float* beta  = (const float*)d_in[11];
    float* out = (float*)d_out;

    cudaFuncSetAttribute(node_mma_kernel, cudaFuncAttributeMaxDynamicSharedMemorySize,
                         NODE_SMEM_BYTES);
    cudaFuncSetAttribute(edge_mma_kernel, cudaFuncAttributeMaxDynamicSharedMemorySize,
                         EDGE_SMEM_BYTES);

    node_mma_kernel<<<NSM, NTHREADS, NODE_SMEM_BYTES>>>(nfeat, W_s, W_d);
    edge_mma_kernel<<<NSM * 2, ETHREADS, EDGE_SMEM_BYTES>>>(efeat, src, dst, W_e, b1,
                                                            W_o, b_o, gamma, beta, out);
    cudaMemcpyAsync(out + (size_t)NE * DIM, nfeat,
                    (size_t)NN * DIM * sizeof(float), cudaMemcpyDeviceToDevice);
}

// round 16
// speedup vs baseline: 1.2023x; 1.2023x over previous
#include <cuda_runtime.h>
#include <cuda_fp16.h>
#include <cstdint>

#define NE 600000
#define NN 50000
#define DIM 128
#define NTHREADS 1024
#define ETHREADS 512
#define ETM 128
#define NSM 152

// Scratch for node projections (fp16 storage halves gather traffic)
__device__ __half g_sproj[(size_t)NN * DIM];
__device__ __half g_dproj[(size_t)NN * DIM];

// ---------------- common helpers ----------------
__device__ __forceinline__ uint32_t smem_u32(const void* p) {
    uint32_t a;
    asm("{ .reg .u64 t; cvta.to.shared.u64 t, %1; cvt.u32.u64 %0, t; }" : "=r"(a) : "l"(p));
    return a;
}

// Swizzled tile layout: rows x 128 fp16, row stride 256B.
// 16B chunk index c (0..15) -> (c&8) | ((c ^ r) & 7): ldmatrix conflict-free.
__device__ __forceinline__ uint32_t swz(int r, int kb) {
    int chunk = kb >> 4;
    int c2 = (chunk & 8) | ((chunk ^ r) & 7);
    return (uint32_t)(r * 256 + c2 * 16 + (kb & 15));
}

__device__ __forceinline__ uint32_t h2u(__half2 h) {
    return *reinterpret_cast<uint32_t*>(&h);
}

// load 128x128 fp32 row-major matrix, convert to fp16 swizzled tile (8B stores)
__device__ __forceinline__ void load_matrix_f16(char* dstB, const float* __restrict__ W,
                                                int t, int nthr) {
    for (int p = t; p < DIM * (DIM / 4); p += nthr) {
        int r = p >> 5, c4 = p & 31;
        float4 v = reinterpret_cast<const float4*>(W)[p];
        uint32_t o = swz(r, c4 * 8);
        *reinterpret_cast<uint2*>(dstB + o) =
            make_uint2(h2u(__floats2half2_rn(v.x, v.y)), h2u(__floats2half2_rn(v.z, v.w)));
    }
}

__device__ __forceinline__ void ldsm4(uint32_t addr, uint32_t r[4]) {
    asm volatile("ldmatrix.sync.aligned.m8n8.x4.shared.b16 {%0,%1,%2,%3}, [%4];"
                 : "=r"(r[0]), "=r"(r[1]), "=r"(r[2]), "=r"(r[3]) : "r"(addr));
}
__device__ __forceinline__ void stsm4(uint32_t addr, uint32_t r0, uint32_t r1,
                                      uint32_t r2, uint32_t r3) {
    asm volatile("stmatrix.sync.aligned.m8n8.x4.shared.b16 [%0], {%1,%2,%3,%4};"
                 :: "r"(addr), "r"(r0), "r"(r1), "r"(r2), "r"(r3) : "memory");
}
__device__ __forceinline__ void mma16816(float c[4], const uint32_t a[4],
                                         uint32_t b0, uint32_t b1) {
    asm volatile("mma.sync.aligned.m16n8k16.row.col.f32.f16.f16.f32 "
                 "{%0,%1,%2,%3}, {%4,%5,%6,%7}, {%8,%9}, {%0,%1,%2,%3};"
                 : "+f"(c[0]), "+f"(c[1]), "+f"(c[2]), "+f"(c[3])
                 : "r"(a[0]), "r"(a[1]), "r"(a[2]), "r"(a[3]), "r"(b0), "r"(b1));
}

// Warp GEMM: D(M32xN32) = A(M32xK128) * W^T(K128xN32), single fp16 term.
__device__ __forceinline__ void warp_gemm_f16_n32(
    uint32_t aB, uint32_t wB, int wm, int wn, int lane, float acc[2][4][4])
{
    #pragma unroll
    for (int mt = 0; mt < 2; mt++)
        #pragma unroll
        for (int n8 = 0; n8 < 4; n8++)
            #pragma unroll
            for (int c = 0; c < 4; c++) acc[mt][n8][c] = 0.f;

    int arow[2];
    #pragma unroll
    for (int mt = 0; mt < 2; mt++)
        arow[mt] = wm * 32 + mt * 16 + ((lane >> 3) & 1) * 8 + (lane & 7);
    const int akhi = (lane >> 4) * 8;
    int brow[2];
    #pragma unroll
    for (int np = 0; np < 2; np++)
        brow[np] = wn * 32 + np * 16 + (lane >> 4) * 8 + (lane & 7);
    const int bkhi = ((lane >> 3) & 1) * 8;

    #pragma unroll
    for (int ks = 0; ks < 8; ks++) {
        const int k0 = ks * 16;
        uint32_t a[2][4], b[2][4];
        #pragma unroll
        for (int mt = 0; mt < 2; mt++)
            ldsm4(aB + swz(arow[mt], (k0 + akhi) * 2), a[mt]);
        #pragma unroll
        for (int np = 0; np < 2; np++)
            ldsm4(wB + swz(brow[np], (k0 + bkhi) * 2), b[np]);
        #pragma unroll
        for (int np = 0; np < 2; np++)
            #pragma unroll
            for (int mt = 0; mt < 2; mt++) {
                mma16816(acc[mt][2 * np],     a[mt], b[np][0], b[np][1]);
                mma16816(acc[mt][2 * np + 1], a[mt], b[np][2], b[np][3]);
            }
    }
}

// Warp GEMM: D(M32xN16), node kernel (4x8 warp grid, 1024 threads).
__device__ __forceinline__ void warp_gemm_f16_n16(
    uint32_t aB, uint32_t wB, int wm, int wn, int lane, float acc[2][2][4])
{
    #pragma unroll
    for (int mt = 0; mt < 2; mt++)
        #pragma unroll
        for (int n8 = 0; n8 < 2; n8++)
            #pragma unroll
            for (int c = 0; c < 4; c++) acc[mt][n8][c] = 0.f;

    int arow[2];
    #pragma unroll
    for (int mt = 0; mt < 2; mt++)
        arow[mt] = wm * 32 + mt * 16 + ((lane >> 3) & 1) * 8 + (lane & 7);
    const int akhi = (lane >> 4) * 8;
    const int brow = wn * 16 + (lane >> 4) * 8 + (lane & 7);
    const int bkhi = ((lane >> 3) & 1) * 8;

    #pragma unroll
    for (int ks = 0; ks < 8; ks++) {
        const int k0 = ks * 16;
        uint32_t a[2][4], b[4];
        #pragma unroll
        for (int mt = 0; mt < 2; mt++)
            ldsm4(aB + swz(arow[mt], (k0 + akhi) * 2), a[mt]);
        ldsm4(wB + swz(brow, (k0 + bkhi) * 2), b);
        #pragma unroll
        for (int mt = 0; mt < 2; mt++) {
            mma16816(acc[mt][0], a[mt], b[0], b[1]);
            mma16816(acc[mt][1], a[mt], b[2], b[3]);
        }
    }
}

// ====== tensor node kernel (fp16 single-term; also writes nfeat passthrough) ======
#define NOFF_WS 0
#define NOFF_WD 32768
#define NOFF_A  65536
#define NODE_SMEM_BYTES (98304 + 1024)
#define NTILES_N ((NN + 127) / 128)

__global__ void __launch_bounds__(NTHREADS, 1)
node_mma_kernel(const float* __restrict__ nfeat,
                const float* __restrict__ W_s, const float* __restrict__ W_d,
                float* __restrict__ outN)
{
    extern __shared__ char smem_raw[];
    char* ab = (char*)(((uintptr_t)smem_raw + 1023) & ~(uintptr_t)1023);
    const int t = threadIdx.x;
    const int wid = t >> 5, lane = t & 31;
    const int wm = wid & 3, wn = wid >> 2;
    const int quad = lane >> 2, qt = lane & 3;

    const uint32_t u_a  = smem_u32(ab + NOFF_A);
    const uint32_t u_ws = smem_u32(ab + NOFF_WS);
    const uint32_t u_wd = smem_u32(ab + NOFF_WD);

    load_matrix_f16(ab + NOFF_WS, W_s, t, NTHREADS);
    load_matrix_f16(ab + NOFF_WD, W_d, t, NTHREADS);

    for (int tile = blockIdx.x; tile < NTILES_N; tile += gridDim.x) {
        const int n0 = tile * 128;
        __syncthreads();
        for (int p = t; p < DIM * 32; p += NTHREADS) {
            int r = p >> 5, c4 = p & 31;
            int n = n0 + r;
            float4 v = make_float4(0.f, 0.f, 0.f, 0.f);
            if (n < NN) {
                v = reinterpret_cast<const float4*>(nfeat)[(size_t)n * 32 + c4];
                // fused nfeat passthrough (replaces cudaMemcpyAsync)
                reinterpret_cast<float4*>(outN)[(size_t)n * 32 + c4] = v;
            }
            uint32_t o = swz(r, c4 * 8);
            *reinterpret_cast<uint2*>(ab + NOFF_A + o) =
                make_uint2(h2u(__floats2half2_rn(v.x, v.y)),
                           h2u(__floats2half2_rn(v.z, v.w)));
        }
        __syncthreads();

        float acc[2][2][4];
        warp_gemm_f16_n16(u_a, u_ws, wm, wn, lane, acc);
        #pragma unroll
        for (int mt = 0; mt < 2; mt++)
            #pragma unroll
            for (int rh = 0; rh < 2; rh++) {
                int n = n0 + wm * 32 + mt * 16 + quad + rh * 8;
                if (n < NN)
                    #pragma unroll
                    for (int n8 = 0; n8 < 2; n8++) {
                        int col = wn * 16 + n8 * 8 + 2 * qt;
                        *reinterpret_cast<__half2*>(&g_sproj[(size_t)n * DIM + col]) =
                            __floats2half2_rn(acc[mt][n8][rh * 2], acc[mt][n8][rh * 2 + 1]);
                    }
            }

        warp_gemm_f16_n16(u_a, u_wd, wm, wn, lane, acc);
        #pragma unroll
        for (int mt = 0; mt < 2; mt++)
            #pragma unroll
            for (int rh = 0; rh < 2; rh++) {
                int n = n0 + wm * 32 + mt * 16 + quad + rh * 8;
                if (n < NN)
                    #pragma unroll
                    for (int n8 = 0; n8 < 2; n8++) {
                        int col = wn * 16 + n8 * 8 + 2 * qt;
                        *reinterpret_cast<__half2*>(&g_dproj[(size_t)n * DIM + col]) =
                            __floats2half2_rn(acc[mt][n8][rh * 2], acc[mt][n8][rh * 2 + 1]);
                    }
            }
    }
}

// ====== mma.sync edge kernel (fp16 single-term, 512 threads, 2 CTAs/SM) ======
#define OFF_W1   0
#define OFF_W2   32768
#define OFF_A    65536    // 128*256 = 32768
#define OFF_B1   98304
#define OFF_BO   98816
#define OFF_GM   99328
#define OFF_BT   99840
#define OFF_RSUM 100352   // float[4][128] = 2048
#define OFF_RSQ  102400   // 2048
#define OFF_SRC  104448   // int[128]
#define OFF_DST  104960
#define EDGE_SMEM_BYTES (105472 + 1024)

#define NTILES_E ((NE + ETM - 1) / ETM)   // 4688

__global__ void __launch_bounds__(ETHREADS, 2)
edge_mma_kernel(const float* __restrict__ efeat,
                const int* __restrict__ src, const int* __restrict__ dst,
                const float* __restrict__ W_e, const float* __restrict__ b1,
                const float* __restrict__ W_o, const float* __restrict__ b_o,
                const float* __restrict__ gamma, const float* __restrict__ beta,
                float* __restrict__ out)
{
    extern __shared__ char smem_raw[];
    char* ab = (char*)(((uintptr_t)smem_raw + 1023) & ~(uintptr_t)1023);
    const int t = threadIdx.x;
    const int wid = t >> 5, lane = t & 31;
    const int wm = wid & 3, wn = wid >> 2;   // 4(M) x 4(N) warp grid, M32 x N32 tiles

    const uint32_t u_a  = smem_u32(ab + OFF_A);
    const uint32_t u_w1 = smem_u32(ab + OFF_W1);
    const uint32_t u_w2 = smem_u32(ab + OFF_W2);

    float* b1s = (float*)(ab + OFF_B1);
    float* bos = (float*)(ab + OFF_BO);
    float* gms = (float*)(ab + OFF_GM);
    float* bts = (float*)(ab + OFF_BT);
    float* rsum = (float*)(ab + OFF_RSUM);
    float* rsq  = (float*)(ab + OFF_RSQ);
    int* srcS = (int*)(ab + OFF_SRC);
    int* dstS = (int*)(ab + OFF_DST);

    load_matrix_f16(ab + OFF_W1, W_e, t, ETHREADS);
    load_matrix_f16(ab + OFF_W2, W_o, t, ETHREADS);
    if (t < 128) { b1s[t] = b1[t]; bos[t] = b_o[t]; gms[t] = gamma[t]; bts[t] = beta[t]; }

    const int quad = lane >> 2, qt = lane & 3;

    for (int tile = blockIdx.x; tile < NTILES_E; tile += gridDim.x) {
        const int e0 = tile * ETM;
        __syncthreads();  // previous tile fully consumed

        // ---- load + convert efeat tile (8B merged stores); load indices
        for (int p = t; p < ETM * 32; p += ETHREADS) {
            int r = p >> 5, c4 = p & 31;
            int e = e0 + r;
            float4 v = make_float4(0.f, 0.f, 0.f, 0.f);
            if (e < NE) v = reinterpret_cast<const float4*>(efeat)[(size_t)e * 32 + c4];
            uint32_t o = swz(r, c4 * 8);
            *reinterpret_cast<uint2*>(ab + OFF_A + o) =
                make_uint2(h2u(__floats2half2_rn(v.x, v.y)),
                           h2u(__floats2half2_rn(v.z, v.w)));
        }
        if (t < ETM) {
            int e = e0 + t;
            srcS[t] = (e < NE) ? src[e] : 0;
            dstS[t] = (e < NE) ? dst[e] : 0;
        }
        __syncthreads();

        // ---- GEMM1
        float acc[2][4][4];
        warp_gemm_f16_n32(u_a, u_w1, wm, wn, lane, acc);
        __syncthreads();  // all warps done reading A before H overwrite

        // ---- epilogue 1: + b1 + gathers (fp16 tables), SiLU (exp), stmatrix -> H
        #pragma unroll
        for (int mt = 0; mt < 2; mt++) {
            uint32_t hh[4][2];  // [n8][rh] packed half2
            #pragma unroll
            for (int rh = 0; rh < 2; rh++) {
                int row = wm * 32 + mt * 16 + quad + rh * 8;
                const __half2* sp = reinterpret_cast<const __half2*>(
                    g_sproj + (size_t)srcS[row] * DIM);
                const __half2* dp = reinterpret_cast<const __half2*>(
                    g_dproj + (size_t)dstS[row] * DIM);
                #pragma unroll
                for (int n8 = 0; n8 < 4; n8++) {
                    int col = wn * 32 + n8 * 8 + 2 * qt;
                    float2 s2 = __half22float2(sp[col >> 1]);
                    float2 d2 = __half22float2(dp[col >> 1]);
                    float2 b2 = *reinterpret_cast<const float2*>(&b1s[col]);
                    float x0 = acc[mt][n8][rh * 2 + 0] + b2.x + s2.x + d2.x;
                    float x1 = acc[mt][n8][rh * 2 + 1] + b2.y + s2.y + d2.y;
                    float v0 = x0 / (1.0f + __expf(-x0));
                    float v1 = x1 / (1.0f + __expf(-x1));
                    hh[n8][rh] = h2u(__floats2half2_rn(v0, v1));
                }
            }
            // 2 x stmatrix.x4: tiles ordered (rh0,2j),(rh1,2j),(rh0,2j+1),(rh1,2j+1)
            #pragma unroll
            for (int j = 0; j < 2; j++) {
                int g = lane >> 3, i = lane & 7;
                int trh = g & 1, tn8 = 2 * j + (g >> 1);
                int r = wm * 32 + mt * 16 + trh * 8 + i;
                int c = wn * 32 + tn8 * 8;
                stsm4(u_a + swz(r, c * 2), hh[2 * j][0], hh[2 * j][1],
                      hh[2 * j + 1][0], hh[2 * j + 1][1]);
            }
        }
        __syncthreads();

        // ---- GEMM2
        warp_gemm_f16_n32(u_a, u_w2, wm, wn, lane, acc);

        // ---- epilogue 2: + b_o, LayerNorm partials (32-col group per warp)
        #pragma unroll
        for (int mt = 0; mt < 2; mt++) {
            #pragma unroll
            for (int rh = 0; rh < 2; rh++) {
                int row = wm * 32 + mt * 16 + quad + rh * 8;
                float s = 0.f, q = 0.f;
                #pragma unroll
                for (int n8 = 0; n8 < 4; n8++) {
                    int col = wn * 32 + n8 * 8 + 2 * qt;
                    float2 b2 = *reinterpret_cast<const float2*>(&bos[col]);
                    float v0 = acc[mt][n8][rh * 2 + 0] + b2.x;
                    float v1 = acc[mt][n8][rh * 2 + 1] + b2.y;
                    acc[mt][n8][rh * 2 + 0] = v0;
                    acc[mt][n8][rh * 2 + 1] = v1;
                    s += v0 + v1;
                    q += v0 * v0 + v1 * v1;
                }
                s += __shfl_xor_sync(0xffffffffu, s, 1);
                s += __shfl_xor_sync(0xffffffffu, s, 2);
                q += __shfl_xor_sync(0xffffffffu, q, 1);
                q += __shfl_xor_sync(0xffffffffu, q, 2);
                if (qt == 0) {
                    rsum[wn * ETM + row] = s;
                    rsq[wn * ETM + row] = q;
                }
            }
        }
        __syncthreads();

        // ---- normalize + affine + residual + store
        #pragma unroll
        for (int mt = 0; mt < 2; mt++) {
            #pragma unroll
            for (int rh = 0; rh < 2; rh++) {
                int row = wm * 32 + mt * 16 + quad + rh * 8;
                int e = e0 + row;
                if (e >= NE) continue;
                float ts = rsum[row] + rsum[ETM + row] + rsum[2 * ETM + row] + rsum[3 * ETM + row];
                float tq = rsq[row] + rsq[ETM + row] + rsq[2 * ETM + row] + rsq[3 * ETM + row];
                float mean = ts * (1.0f / 128.0f);
                float var = tq * (1.0f / 128.0f) - mean * mean;
                float rstd = rsqrtf(var + 1e-5f);
                #pragma unroll
                for (int n8 = 0; n8 < 4; n8++) {
                    int col = wn * 32 + n8 * 8 + 2 * qt;
                    float2 g2 = *reinterpret_cast<const float2*>(&gms[col]);
                    float2 t2 = *reinterpret_cast<const float2*>(&bts[col]);
                    float2 r2 = *reinterpret_cast<const float2*>(&efeat[(size_t)e * DIM + col]);
                    float o0 = (acc[mt][n8][rh * 2 + 0] - mean) * rstd * g2.x + t2.x + r2.x;
                    float o1 = (acc[mt][n8][rh * 2 + 1] - mean) * rstd * g2.y + t2.y + r2.y;
                    *reinterpret_cast<float2*>(&out[(size_t)e * DIM + col]) = make_float2(o0, o1);
                }
            }
        }
    }
}

extern "C" void kernel_launch(void* const* d_in, const int* in_sizes, int n_in,
                              void* d_out, int out_size) {
    const float* efeat = (const float*)d_in[0];
    const float* nfeat = (const float*)d_in[1];
    const int*   src   = (const int*)d_in[2];
    const int*   dst   = (const int*)d_in[3];
    const float* W_e   = (const float*)d_in[4];
    const float* W_s   = (const float*)d_in[5];
    const float* W_d   = (const float*)d_in[6];
    const float* b1    = (const float*)d_in[7];
    const float* W_o   = (const float*)d_in[8];
    const float* b_o   = (const float*)d_in[9];
    const float* gamma = (const float*)d_in[10];
    const float* beta  = (const float*)d_in[11];
    float* out = (float*)d_out;

    cudaFuncSetAttribute(node_mma_kernel, cudaFuncAttributeMaxDynamicSharedMemorySize,
                         NODE_SMEM_BYTES);
    cudaFuncSetAttribute(edge_mma_kernel, cudaFuncAttributeMaxDynamicSharedMemorySize,
                         EDGE_SMEM_BYTES);

    node_mma_kernel<<<NSM, NTHREADS, NODE_SMEM_BYTES>>>(nfeat, W_s, W_d,
                                                        out + (size_t)NE * DIM);
    edge_mma_kernel<<<NSM * 2, ETHREADS, EDGE_SMEM_BYTES>>>(efeat, src, dst, W_e, b1,
                                                            W_o, b_o, gamma, beta, out);
}